// round 11
// baseline (speedup 1.0000x reference)
#include <cuda_runtime.h>
#include <cuda_bf16.h>

#define TSEQ   2048
#define BATCH  4096
#define HDIM   32
#define STAGE  16
#define NSTAGE (TSEQ / STAGE)
#define NBMAX  4
#define NB28BLOCKS 100   // blocks carrying 28 rows; remaining 48 carry 27

typedef unsigned long long ull;

// ---------- packed f32x2 helpers ----------
__device__ __forceinline__ ull pack2(float lo, float hi) {
    ull r;
    asm("mov.b64 %0, {%1, %2};" : "=l"(r) : "f"(lo), "f"(hi));
    return r;
}
__device__ __forceinline__ void unpack2(ull v, float& lo, float& hi) {
    asm("mov.b64 {%0, %1}, %2;" : "=f"(lo), "=f"(hi) : "l"(v));
}
__device__ __forceinline__ ull ffma2(ull a, ull b, ull c) {
    ull d;
    asm("fma.rn.f32x2 %0, %1, %2, %3;" : "=l"(d) : "l"(a), "l"(b), "l"(c));
    return d;
}
__device__ __forceinline__ ull mul2(ull a, ull b) {
    ull d;
    asm("mul.rn.f32x2 %0, %1, %2;" : "=l"(d) : "l"(a), "l"(b));
    return d;
}
__device__ __forceinline__ ull add2(ull a, ull b) {
    ull d;
    asm("add.rn.f32x2 %0, %1, %2;" : "=l"(d) : "l"(a), "l"(b));
    return d;
}
// 4-byte async copy global -> shared (no destination register)
__device__ __forceinline__ void cp_async4(unsigned int saddr, const void* gaddr) {
    asm volatile("cp.async.ca.shared.global [%0], [%1], 4;"
                 :: "r"(saddr), "l"(gaddr));
}
__device__ __forceinline__ void cp_async_commit() {
    asm volatile("cp.async.commit_group;");
}
__device__ __forceinline__ void cp_async_wait0() {
    asm volatile("cp.async.wait_group 0;");
}

// ---------- single-MUFU tanh (sm_75+) ----------
__device__ __forceinline__ float tanhf_fast(float x) {
    float y;
    asm("tanh.approx.f32 %0, %1;" : "=f"(y) : "f"(x));
    return y;
}
// sigmoid(x) = 0.5*tanh(x/2) + 0.5 ; the /2 pre-folded into weights+bias.
__device__ __forceinline__ float sig_from_half(float xh) {
    return fmaf(0.5f, tanhf_fast(xh), 0.5f);
}

// One warp processes NB batch rows through all 2048 steps.
// ROW-SEQUENTIAL inner loop: row b's matvec (4 chains) then row b's
// activations — ptxas interleaves act(b) MUFUs into matvec(b+1)'s FFMA2
// stream, spreading MUFU/FMA pressure through the step.
// Gates packed (i,f),(g,o) into f32x2; sigmoid rows pre-scaled by 0.5.
// W_hh fully register-resident (128 regs/lane).
template <int NB>
__device__ __forceinline__ void lstm_run(
    const float* __restrict__ x,
    const float* __restrict__ W_ih,
    const float* __restrict__ W_hh,
    const float* __restrict__ b_ih,
    const float* __restrict__ b_hh,
    float* __restrict__ out,
    ull (*hdup)[NBMAX][HDIM],        // [2][NBMAX][32] this warp's slice
    ull (*xdup)[NBMAX][STAGE][4],    // [2][NBMAX][STAGE][4] double-buffered
    int row0, int lane)
{
    constexpr int NE = NB * STAGE * 3;       // x elements per stage
    constexpr int NI = (NE + 31) / 32;       // cp.async iterations per lane

    // PyTorch gate rows for this lane: i, f, g, o
    const int r0 = lane;             // i  (sigmoid -> 0.5)
    const int r1 = HDIM + lane;      // f  (sigmoid -> 0.5)
    const int r2 = 2 * HDIM + lane;  // g  (tanh    -> 1.0)
    const int r3 = 3 * HDIM + lane;  // o  (sigmoid -> 0.5)

    // ---- recurrent weights into registers, gate-pair packed ----
    ull wif[HDIM], wgo[HDIM];
#pragma unroll
    for (int k = 0; k < HDIM; k++) {
        wif[k] = pack2(0.5f * W_hh[r0 * HDIM + k], 0.5f * W_hh[r1 * HDIM + k]);
        wgo[k] = pack2(       W_hh[r2 * HDIM + k], 0.5f * W_hh[r3 * HDIM + k]);
    }
    // ---- input weights + combined bias ----
    ull wxif[3], wxgo[3];
#pragma unroll
    for (int i = 0; i < 3; i++) {
        wxif[i] = pack2(0.5f * W_ih[r0 * 3 + i], 0.5f * W_ih[r1 * 3 + i]);
        wxgo[i] = pack2(       W_ih[r2 * 3 + i], 0.5f * W_ih[r3 * 3 + i]);
    }
    const ull bias_if = pack2(0.5f * (b_ih[r0] + b_hh[r0]),
                              0.5f * (b_ih[r1] + b_hh[r1]));
    const ull bias_go = pack2(       (b_ih[r2] + b_hh[r2]),
                              0.5f * (b_ih[r3] + b_hh[r3]));

    unsigned int xs_s[2];
    xs_s[0] = (unsigned int)__cvta_generic_to_shared(&xdup[0][0][0][0]);
    xs_s[1] = (unsigned int)__cvta_generic_to_shared(&xdup[1][0][0][0]);

    float c[NB];
#pragma unroll
    for (int b = 0; b < NB; b++) {
        c[b] = 0.0f;
        hdup[0][b][lane] = 0ull;
    }

    // ---- stage 0 of x via cp.async, written pre-duplicated ----
#pragma unroll
    for (int it = 0; it < NI; it++) {
        int idx = it * 32 + lane;
        if (idx < NE) {
            int b   = idx / (STAGE * 3);
            int rem = idx % (STAGE * 3);
            int t   = rem / 3, i = rem % 3;
            const float* g = x + (size_t)(row0 + b) * TSEQ * 3 + rem;
            unsigned int d = xs_s[0] + (unsigned)((b * STAGE + t) * 4 + i) * 8u;
            cp_async4(d,      g);
            cp_async4(d + 4u, g);
        }
    }
    cp_async_commit();
    cp_async_wait0();
    __syncwarp();

    int buf = 0;
#pragma unroll 1
    for (int s = 0; s < NSTAGE; s++) {
        // ---- prefetch next stage into the other buffer (fire and forget) ----
        if (s + 1 < NSTAGE) {
#pragma unroll
            for (int it = 0; it < NI; it++) {
                int idx = it * 32 + lane;
                if (idx < NE) {
                    int b   = idx / (STAGE * 3);
                    int rem = idx % (STAGE * 3);
                    int t   = rem / 3, i = rem % 3;
                    const float* g = x + (size_t)(row0 + b) * TSEQ * 3
                                       + (size_t)(s + 1) * STAGE * 3 + rem;
                    unsigned int d = xs_s[buf ^ 1] + (unsigned)((b * STAGE + t) * 4 + i) * 8u;
                    cp_async4(d,      g);
                    cp_async4(d + 4u, g);
                }
            }
            cp_async_commit();
        }

#pragma unroll 1
        for (int tt = 0; tt < STAGE; tt++) {
            const int rb = tt & 1;
            const int wb = rb ^ 1;

            // ---- rows sequential: act(b) interleaves into matvec(b+1) ----
#pragma unroll
            for (int b = 0; b < NB; b++) {
                // affine seeds the 4 chains (no zero-init waste)
                ulonglong2 x01 = *reinterpret_cast<const ulonglong2*>(&xdup[buf][b][tt][0]);
                ull x2 = xdup[buf][b][tt][2];
                ull aifA = ffma2(x01.x, wxif[0], bias_if);
                ull agoA = ffma2(x01.x, wxgo[0], bias_go);
                ull aifB = ffma2(x01.y, wxif[1], mul2(x2, wxif[2]));
                ull agoB = ffma2(x01.y, wxgo[1], mul2(x2, wxgo[2]));

                // recurrent matvec: 4 chains, reuse distance 8 cyc >= lat 4
#pragma unroll
                for (int kk = 0; kk < HDIM; kk += 4) {
                    ulonglong2 hd0 = *reinterpret_cast<const ulonglong2*>(&hdup[rb][b][kk]);
                    ulonglong2 hd1 = *reinterpret_cast<const ulonglong2*>(&hdup[rb][b][kk + 2]);
                    aifA = ffma2(wif[kk],     hd0.x, aifA);
                    agoA = ffma2(wgo[kk],     hd0.x, agoA);
                    aifB = ffma2(wif[kk + 1], hd0.y, aifB);
                    agoB = ffma2(wgo[kk + 1], hd0.y, agoB);
                    aifA = ffma2(wif[kk + 2], hd1.x, aifA);
                    agoA = ffma2(wgo[kk + 2], hd1.x, agoA);
                    aifB = ffma2(wif[kk + 3], hd1.y, aifB);
                    agoB = ffma2(wgo[kk + 3], hd1.y, agoB);
                }
                ull tif = add2(aifA, aifB);
                ull tgo = add2(agoA, agoB);

                // activations + state update (i,f,o preacts pre-halved)
                float ih, fh, gp, oh;
                unpack2(tif, ih, fh);
                unpack2(tgo, gp, oh);
                float ig = sig_from_half(ih);
                float fg = sig_from_half(fh);
                float gg = tanhf_fast(gp);
                float og = sig_from_half(oh);
                c[b] = fmaf(fg, c[b], ig * gg);
                float hb = og * tanhf_fast(c[b]);
                hdup[wb][b][lane] = pack2(hb, hb);
            }
            __syncwarp();   // h published before next step's reads
        }

        // ---- flip x buffer once the prefetch has landed ----
        if (s + 1 < NSTAGE) {
            cp_async_wait0();
            __syncwarp();
            buf ^= 1;
        }
    }

    // Last step (tt=15) wrote parity buffer 0.
#pragma unroll
    for (int b = 0; b < NB; b++) {
        float lo, hi;
        unpack2(hdup[0][b][lane], lo, hi);
        out[(size_t)(row0 + b) * HDIM + lane] = lo;
    }
}

// Row distribution within a block. wid%4 -> SMSP, so wid i pairs with wid i+4.
// 28-row blocks: NB = 4,4,4,4,3,3,3,3  -> every SMSP pair carries 4+3 = 7 rows.
// 27-row blocks: NB = 4,4,4,3,3,3,3,3  -> pairs 7,7,7,6.
__device__ __constant__ int NB28[8]  = {4, 4, 4, 4, 3, 3, 3, 3};
__device__ __constant__ int OFF28[8] = {0, 4, 8, 12, 16, 19, 22, 25};
__device__ __constant__ int NB27[8]  = {4, 4, 4, 3, 3, 3, 3, 3};
__device__ __constant__ int OFF27[8] = {0, 4, 8, 12, 15, 18, 21, 24};

// 148 blocks x 256 threads: one block per SM, 2 warps per SMSP with
// controlled pairing; single wave, zero tail.
__global__ void __launch_bounds__(256, 1)
lstm_kernel(const float* __restrict__ x,
            const float* __restrict__ W_ih,
            const float* __restrict__ W_hh,
            const float* __restrict__ b_ih,
            const float* __restrict__ b_hh,
            float* __restrict__ out)
{
    __shared__ __align__(16) ull hd[8][2][NBMAX][HDIM];
    __shared__ __align__(16) ull xd[8][2][NBMAX][STAGE][4];

    const int wid  = threadIdx.x >> 5;
    const int lane = threadIdx.x & 31;
    const int bid  = blockIdx.x;

    int row0, nb;
    if (bid < NB28BLOCKS) {
        row0 = bid * 28 + OFF28[wid];
        nb   = NB28[wid];
    } else {
        row0 = NB28BLOCKS * 28 + (bid - NB28BLOCKS) * 27 + OFF27[wid];
        nb   = NB27[wid];
    }

    if (nb == 4) {
        lstm_run<4>(x, W_ih, W_hh, b_ih, b_hh, out, hd[wid], xd[wid], row0, lane);
    } else {
        lstm_run<3>(x, W_ih, W_hh, b_ih, b_hh, out, hd[wid], xd[wid], row0, lane);
    }
}

extern "C" void kernel_launch(void* const* d_in, const int* in_sizes, int n_in,
                              void* d_out, int out_size)
{
    const float* x    = (const float*)d_in[0];
    const float* W_ih = (const float*)d_in[1];
    const float* W_hh = (const float*)d_in[2];
    const float* b_ih = (const float*)d_in[3];
    const float* b_hh = (const float*)d_in[4];
    float* out = (float*)d_out;

    lstm_kernel<<<148, 256>>>(x, W_ih, W_hh, b_ih, b_hh, out);
}

// round 12
// speedup vs baseline: 1.2449x; 1.2449x over previous
#include <cuda_runtime.h>
#include <cuda_bf16.h>

#define TSEQ   2048
#define BATCH  4096
#define HDIM   32
#define STAGE  16
#define NSTAGE (TSEQ / STAGE)
#define NBMAX  4
#define NB28BLOCKS 100   // blocks carrying 28 rows; remaining 48 carry 27

typedef unsigned long long ull;

// ---------- packed f32x2 helpers ----------
__device__ __forceinline__ ull pack2(float lo, float hi) {
    ull r;
    asm("mov.b64 %0, {%1, %2};" : "=l"(r) : "f"(lo), "f"(hi));
    return r;
}
__device__ __forceinline__ void unpack2(ull v, float& lo, float& hi) {
    asm("mov.b64 {%0, %1}, %2;" : "=f"(lo), "=f"(hi) : "l"(v));
}
__device__ __forceinline__ ull ffma2(ull a, ull b, ull c) {
    ull d;
    asm("fma.rn.f32x2 %0, %1, %2, %3;" : "=l"(d) : "l"(a), "l"(b), "l"(c));
    return d;
}
// 4-byte async copy global -> shared (no destination register)
__device__ __forceinline__ void cp_async4(unsigned int saddr, const void* gaddr) {
    asm volatile("cp.async.ca.shared.global [%0], [%1], 4;"
                 :: "r"(saddr), "l"(gaddr));
}
__device__ __forceinline__ void cp_async_commit() {
    asm volatile("cp.async.commit_group;");
}
__device__ __forceinline__ void cp_async_wait0() {
    asm volatile("cp.async.wait_group 0;");
}

// ---------- single-MUFU tanh (sm_75+) ----------
__device__ __forceinline__ float tanhf_fast(float x) {
    float y;
    asm("tanh.approx.f32 %0, %1;" : "=f"(y) : "f"(x));
    return y;
}
// sigmoid(x) = 0.5*tanh(x/2) + 0.5 ; the /2 pre-folded into weights+bias.
__device__ __forceinline__ float sig_from_half(float xh) {
    return fmaf(0.5f, tanhf_fast(xh), 0.5f);
}

// One warp processes NB batch rows through all 2048 steps.
// DUPLICATION-FREE k-packed layout: h stored as plain f32; one ulonglong2
// load gives two ready f32x2 operands (adjacent k pairs). Weights packed over
// adjacent k per gate. 4 accumulators per row (16 chains). Horizontal FADD
// merges even/odd partial sums. Sigmoid rows pre-scaled by 0.5.
// W_hh fully register-resident (128 regs/lane).
template <int NB>
__device__ __forceinline__ void lstm_run(
    const float* __restrict__ x,
    const float* __restrict__ W_ih,
    const float* __restrict__ W_hh,
    const float* __restrict__ b_ih,
    const float* __restrict__ b_hh,
    float* __restrict__ out,
    float (*hs)[NBMAX][HDIM],        // [2][NBMAX][32] plain f32, parity-buffered
    float (*xs)[NBMAX][STAGE][4],    // [2][NBMAX][16][4] double-buffered
    int row0, int lane)
{
    constexpr int NE = NB * STAGE * 3;       // x elements per stage
    constexpr int NI = (NE + 31) / 32;       // cp.async iterations per lane

    // PyTorch gate rows for this lane: i, f, g, o
    const int r0 = lane;             // i  (sigmoid -> 0.5)
    const int r1 = HDIM + lane;      // f  (sigmoid -> 0.5)
    const int r2 = 2 * HDIM + lane;  // g  (tanh    -> 1.0)
    const int r3 = 3 * HDIM + lane;  // o  (sigmoid -> 0.5)

    // ---- recurrent weights, packed over adjacent k per gate ----
    ull wkI[16], wkF[16], wkG[16], wkO[16];
#pragma unroll
    for (int m = 0; m < 16; m++) {
        wkI[m] = pack2(0.5f * W_hh[r0 * HDIM + 2 * m], 0.5f * W_hh[r0 * HDIM + 2 * m + 1]);
        wkF[m] = pack2(0.5f * W_hh[r1 * HDIM + 2 * m], 0.5f * W_hh[r1 * HDIM + 2 * m + 1]);
        wkG[m] = pack2(       W_hh[r2 * HDIM + 2 * m],        W_hh[r2 * HDIM + 2 * m + 1]);
        wkO[m] = pack2(0.5f * W_hh[r3 * HDIM + 2 * m], 0.5f * W_hh[r3 * HDIM + 2 * m + 1]);
    }
    // ---- input weights + combined bias (scalars) ----
    float wxi[3], wxf[3], wxg[3], wxo[3];
#pragma unroll
    for (int i = 0; i < 3; i++) {
        wxi[i] = 0.5f * W_ih[r0 * 3 + i];
        wxf[i] = 0.5f * W_ih[r1 * 3 + i];
        wxg[i] =        W_ih[r2 * 3 + i];
        wxo[i] = 0.5f * W_ih[r3 * 3 + i];
    }
    const float bI = 0.5f * (b_ih[r0] + b_hh[r0]);
    const float bF = 0.5f * (b_ih[r1] + b_hh[r1]);
    const float bG =        (b_ih[r2] + b_hh[r2]);
    const float bO = 0.5f * (b_ih[r3] + b_hh[r3]);

    unsigned int xs_s[2];
    xs_s[0] = (unsigned int)__cvta_generic_to_shared(&xs[0][0][0][0]);
    xs_s[1] = (unsigned int)__cvta_generic_to_shared(&xs[1][0][0][0]);

    float c[NB];
#pragma unroll
    for (int b = 0; b < NB; b++) {
        c[b] = 0.0f;
        hs[0][b][lane] = 0.0f;
    }

    // ---- stage 0 of x via cp.async (single copy, no duplication) ----
#pragma unroll
    for (int it = 0; it < NI; it++) {
        int idx = it * 32 + lane;
        if (idx < NE) {
            int b   = idx / (STAGE * 3);
            int rem = idx % (STAGE * 3);
            int t   = rem / 3, i = rem % 3;
            cp_async4(xs_s[0] + (unsigned)((b * STAGE + t) * 4 + i) * 4u,
                      x + (size_t)(row0 + b) * TSEQ * 3 + rem);
        }
    }
    cp_async_commit();
    cp_async_wait0();
    __syncwarp();

    int buf = 0;
#pragma unroll 1
    for (int s = 0; s < NSTAGE; s++) {
        // ---- prefetch next stage into the other buffer (fire and forget) ----
        if (s + 1 < NSTAGE) {
#pragma unroll
            for (int it = 0; it < NI; it++) {
                int idx = it * 32 + lane;
                if (idx < NE) {
                    int b   = idx / (STAGE * 3);
                    int rem = idx % (STAGE * 3);
                    int t   = rem / 3, i = rem % 3;
                    cp_async4(xs_s[buf ^ 1] + (unsigned)((b * STAGE + t) * 4 + i) * 4u,
                              x + (size_t)(row0 + b) * TSEQ * 3
                                + (size_t)(s + 1) * STAGE * 3 + rem);
                }
            }
            cp_async_commit();
        }

#pragma unroll 1
        for (int tt = 0; tt < STAGE; tt++) {
            const int rb = tt & 1;
            const int wb = rb ^ 1;

            // ---- affine seeds accumulators as (aff, 0) ----
            ull accI[NB], accF[NB], accG[NB], accO[NB];
#pragma unroll
            for (int b = 0; b < NB; b++) {
                float4 xv = *reinterpret_cast<const float4*>(&xs[buf][b][tt][0]);
                accI[b] = pack2(fmaf(xv.x, wxi[0], fmaf(xv.y, wxi[1], fmaf(xv.z, wxi[2], bI))), 0.0f);
                accF[b] = pack2(fmaf(xv.x, wxf[0], fmaf(xv.y, wxf[1], fmaf(xv.z, wxf[2], bF))), 0.0f);
                accG[b] = pack2(fmaf(xv.x, wxg[0], fmaf(xv.y, wxg[1], fmaf(xv.z, wxg[2], bG))), 0.0f);
                accO[b] = pack2(fmaf(xv.x, wxo[0], fmaf(xv.y, wxo[1], fmaf(xv.z, wxo[2], bO))), 0.0f);
            }

            // ---- recurrent matvec: kk-outer (8 groups of 4 k), rows inner.
            // One ulonglong2 load = 2 f32x2 operands of DISTINCT adjacent h. ----
#pragma unroll
            for (int g = 0; g < 8; g++) {
#pragma unroll
                for (int b = 0; b < NB; b++) {
                    ulonglong2 hd = *reinterpret_cast<const ulonglong2*>(&hs[rb][b][4 * g]);
                    accI[b] = ffma2(wkI[2 * g],     hd.x, accI[b]);
                    accF[b] = ffma2(wkF[2 * g],     hd.x, accF[b]);
                    accG[b] = ffma2(wkG[2 * g],     hd.x, accG[b]);
                    accO[b] = ffma2(wkO[2 * g],     hd.x, accO[b]);
                    accI[b] = ffma2(wkI[2 * g + 1], hd.y, accI[b]);
                    accF[b] = ffma2(wkF[2 * g + 1], hd.y, accF[b]);
                    accG[b] = ffma2(wkG[2 * g + 1], hd.y, accG[b]);
                    accO[b] = ffma2(wkO[2 * g + 1], hd.y, accO[b]);
                }
            }

            // ---- horizontal merge + activations + state update ----
#pragma unroll
            for (int b = 0; b < NB; b++) {
                float ilo, ihi, flo, fhi, glo, ghi, olo, ohi;
                unpack2(accI[b], ilo, ihi);
                unpack2(accF[b], flo, fhi);
                unpack2(accG[b], glo, ghi);
                unpack2(accO[b], olo, ohi);
                float ig = sig_from_half(ilo + ihi);
                float fg = sig_from_half(flo + fhi);
                float gg = tanhf_fast(glo + ghi);
                float og = sig_from_half(olo + ohi);
                c[b] = fmaf(fg, c[b], ig * gg);
                hs[wb][b][lane] = og * tanhf_fast(c[b]);
            }
            __syncwarp();   // h published before next step's reads
        }

        // ---- flip x buffer once the prefetch has landed ----
        if (s + 1 < NSTAGE) {
            cp_async_wait0();
            __syncwarp();
            buf ^= 1;
        }
    }

    // Last step (tt=15) wrote parity buffer 0.
#pragma unroll
    for (int b = 0; b < NB; b++)
        out[(size_t)(row0 + b) * HDIM + lane] = hs[0][b][lane];
}

// Row distribution within a block. wid%4 -> SMSP, so wid i pairs with wid i+4.
// 28-row blocks: NB = 4,4,4,4,3,3,3,3  -> every SMSP pair carries 4+3 = 7 rows.
// 27-row blocks: NB = 4,4,4,3,3,3,3,3  -> pairs 7,7,7,6.
__device__ __constant__ int NB28[8]  = {4, 4, 4, 4, 3, 3, 3, 3};
__device__ __constant__ int OFF28[8] = {0, 4, 8, 12, 16, 19, 22, 25};
__device__ __constant__ int NB27[8]  = {4, 4, 4, 3, 3, 3, 3, 3};
__device__ __constant__ int OFF27[8] = {0, 4, 8, 12, 15, 18, 21, 24};

// 148 blocks x 256 threads: one block per SM, 2 warps per SMSP with
// controlled pairing; single wave, zero tail.
__global__ void __launch_bounds__(256, 1)
lstm_kernel(const float* __restrict__ x,
            const float* __restrict__ W_ih,
            const float* __restrict__ W_hh,
            const float* __restrict__ b_ih,
            const float* __restrict__ b_hh,
            float* __restrict__ out)
{
    __shared__ __align__(16) float hsm[8][2][NBMAX][HDIM];
    __shared__ __align__(16) float xsm[8][2][NBMAX][STAGE][4];

    const int wid  = threadIdx.x >> 5;
    const int lane = threadIdx.x & 31;
    const int bid  = blockIdx.x;

    int row0, nb;
    if (bid < NB28BLOCKS) {
        row0 = bid * 28 + OFF28[wid];
        nb   = NB28[wid];
    } else {
        row0 = NB28BLOCKS * 28 + (bid - NB28BLOCKS) * 27 + OFF27[wid];
        nb   = NB27[wid];
    }

    if (nb == 4) {
        lstm_run<4>(x, W_ih, W_hh, b_ih, b_hh, out, hsm[wid], xsm[wid], row0, lane);
    } else {
        lstm_run<3>(x, W_ih, W_hh, b_ih, b_hh, out, hsm[wid], xsm[wid], row0, lane);
    }
}

extern "C" void kernel_launch(void* const* d_in, const int* in_sizes, int n_in,
                              void* d_out, int out_size)
{
    const float* x    = (const float*)d_in[0];
    const float* W_ih = (const float*)d_in[1];
    const float* W_hh = (const float*)d_in[2];
    const float* b_ih = (const float*)d_in[3];
    const float* b_hh = (const float*)d_in[4];
    float* out = (float*)d_out;

    lstm_kernel<<<148, 256>>>(x, W_ih, W_hh, b_ih, b_hh, out);
}